// round 3
// baseline (speedup 1.0000x reference)
#include <cuda_runtime.h>
#include <math.h>

// Problem shape (fixed by reference):
//   x: [4, 2048, 1024] fp32;  W_key/W_query/W_value: [1024, 1024] fp32 ([out,in])
//   out: context [4, 2048, 1024] fp32
#define BATCH 4
#define SEQ   2048
#define DIM   1024

// ---- scratch (device globals: allocation-free rule) ----
__device__ float g_Q[(long)BATCH * SEQ * DIM];
__device__ float g_K[(long)BATCH * SEQ * DIM];
__device__ float g_V[(long)BATCH * SEQ * DIM];
__device__ float g_S[(long)BATCH * SEQ * SEQ];

// ---- tiled SGEMM params ----
#define BM 128
#define BN 128
#define BK 16
#define TM 8
#define TN 8
#define NTHREADS 256
#define PAD 4   // smem row padding (floats) to break LDS.128 conflicts

// C[M,N] = alpha * A[M,K] @ B[N,K]^T   (both A and B are K-major / row-major)
// batched over blockIdx.z with element strides sA, sB, sC.
__global__ __launch_bounds__(NTHREADS)
void gemm_nt(const float* __restrict__ A, const float* __restrict__ B,
             float* __restrict__ C,
             int M, int N, int K,
             long sA, long sB, long sC, float alpha)
{
    __shared__ float As[BK][BM + PAD];
    __shared__ float Bs[BK][BN + PAD];

    const int tid = threadIdx.x;
    const float* Ab = A + (long)blockIdx.z * sA + (long)blockIdx.y * BM * K;
    const float* Bb = B + (long)blockIdx.z * sB + (long)blockIdx.x * BN * K;
    float*       Cb = C + (long)blockIdx.z * sC;

    const int lr = tid >> 2;        // 0..63  (row within tile, +64 on 2nd pass)
    const int lc = (tid & 3) * 4;   // 0,4,8,12 (k offset, float4)

    const int ty = tid >> 4;        // 0..15
    const int tx = tid & 15;        // 0..15

    float acc[TM][TN];
#pragma unroll
    for (int i = 0; i < TM; i++)
#pragma unroll
        for (int j = 0; j < TN; j++) acc[i][j] = 0.0f;

    for (int k0 = 0; k0 < K; k0 += BK) {
#pragma unroll
        for (int r = 0; r < BM; r += 64) {
            float4 va = *(const float4*)(Ab + (long)(lr + r) * K + k0 + lc);
            As[lc + 0][lr + r] = va.x;
            As[lc + 1][lr + r] = va.y;
            As[lc + 2][lr + r] = va.z;
            As[lc + 3][lr + r] = va.w;
            float4 vb = *(const float4*)(Bb + (long)(lr + r) * K + k0 + lc);
            Bs[lc + 0][lr + r] = vb.x;
            Bs[lc + 1][lr + r] = vb.y;
            Bs[lc + 2][lr + r] = vb.z;
            Bs[lc + 3][lr + r] = vb.w;
        }
        __syncthreads();

#pragma unroll
        for (int k = 0; k < BK; k++) {
            float am[TM], bn[TN];
            *(float4*)&am[0] = *(const float4*)&As[k][ty * TM];
            *(float4*)&am[4] = *(const float4*)&As[k][ty * TM + 4];
            *(float4*)&bn[0] = *(const float4*)&Bs[k][tx * TN];
            *(float4*)&bn[4] = *(const float4*)&Bs[k][tx * TN + 4];
#pragma unroll
            for (int i = 0; i < TM; i++)
#pragma unroll
                for (int j = 0; j < TN; j++)
                    acc[i][j] = fmaf(am[i], bn[j], acc[i][j]);
        }
        __syncthreads();
    }

#pragma unroll
    for (int i = 0; i < TM; i++) {
        long row = (long)blockIdx.y * BM + ty * TM + i;
        float* cp = Cb + row * N + (long)blockIdx.x * BN + tx * TN;
        float4 o0, o1;
        o0.x = acc[i][0] * alpha; o0.y = acc[i][1] * alpha;
        o0.z = acc[i][2] * alpha; o0.w = acc[i][3] * alpha;
        o1.x = acc[i][4] * alpha; o1.y = acc[i][5] * alpha;
        o1.z = acc[i][6] * alpha; o1.w = acc[i][7] * alpha;
        *(float4*)cp = o0;
        *(float4*)(cp + 4) = o1;
    }
}

// C[M,N] = A[M,K] @ B[K,N]   (B row-major, N contiguous), batched via blockIdx.z
__global__ __launch_bounds__(NTHREADS)
void gemm_nn(const float* __restrict__ A, const float* __restrict__ B,
             float* __restrict__ C,
             int M, int N, int K,
             long sA, long sB, long sC)
{
    __shared__ float As[BK][BM + PAD];
    __shared__ float Bs[BK][BN + PAD];

    const int tid = threadIdx.x;
    const float* Ab = A + (long)blockIdx.z * sA + (long)blockIdx.y * BM * K;
    const float* Bb = B + (long)blockIdx.z * sB;
    float*       Cb = C + (long)blockIdx.z * sC;

    const int lr = tid >> 2;        // A loader: row 0..63 (+64)
    const int lc = (tid & 3) * 4;

    const int br = tid >> 5;        // B loader: k-row 0..7 (+8)
    const int bc = (tid & 31) * 4;  // col within BN

    const int ty = tid >> 4;
    const int tx = tid & 15;

    float acc[TM][TN];
#pragma unroll
    for (int i = 0; i < TM; i++)
#pragma unroll
        for (int j = 0; j < TN; j++) acc[i][j] = 0.0f;

    for (int k0 = 0; k0 < K; k0 += BK) {
#pragma unroll
        for (int r = 0; r < BM; r += 64) {
            float4 va = *(const float4*)(Ab + (long)(lr + r) * K + k0 + lc);
            As[lc + 0][lr + r] = va.x;
            As[lc + 1][lr + r] = va.y;
            As[lc + 2][lr + r] = va.z;
            As[lc + 3][lr + r] = va.w;
        }
#pragma unroll
        for (int r = 0; r < BK; r += 8) {
            float4 vb = *(const float4*)(Bb + (long)(k0 + br + r) * N +
                                         (long)blockIdx.x * BN + bc);
            Bs[br + r][bc + 0] = vb.x;
            Bs[br + r][bc + 1] = vb.y;
            Bs[br + r][bc + 2] = vb.z;
            Bs[br + r][bc + 3] = vb.w;
        }
        __syncthreads();

#pragma unroll
        for (int k = 0; k < BK; k++) {
            float am[TM], bn[TN];
            *(float4*)&am[0] = *(const float4*)&As[k][ty * TM];
            *(float4*)&am[4] = *(const float4*)&As[k][ty * TM + 4];
            *(float4*)&bn[0] = *(const float4*)&Bs[k][tx * TN];
            *(float4*)&bn[4] = *(const float4*)&Bs[k][tx * TN + 4];
#pragma unroll
            for (int i = 0; i < TM; i++)
#pragma unroll
                for (int j = 0; j < TN; j++)
                    acc[i][j] = fmaf(am[i], bn[j], acc[i][j]);
        }
        __syncthreads();
    }

#pragma unroll
    for (int i = 0; i < TM; i++) {
        long row = (long)blockIdx.y * BM + ty * TM + i;
        float* cp = Cb + row * N + (long)blockIdx.x * BN + tx * TN;
        *(float4*)cp       = *(float4*)&acc[i][0];
        *(float4*)(cp + 4) = *(float4*)&acc[i][4];
    }
}

// Row softmax over rows of length n (=2048). One block (256 thr) per row.
__global__ __launch_bounds__(256)
void softmax_rows(float* __restrict__ S, int n)
{
    float* row = S + (long)blockIdx.x * n;
    const int tid = threadIdx.x;
    __shared__ float red[8];

    // pass 1: max
    float m = -1e30f;
    for (int i = tid * 4; i < n; i += 256 * 4) {
        float4 v = *(const float4*)(row + i);
        m = fmaxf(m, fmaxf(fmaxf(v.x, v.y), fmaxf(v.z, v.w)));
    }
#pragma unroll
    for (int o = 16; o; o >>= 1) m = fmaxf(m, __shfl_xor_sync(0xffffffffu, m, o));
    if ((tid & 31) == 0) red[tid >> 5] = m;
    __syncthreads();
    if (tid < 32) {
        float v = (tid < 8) ? red[tid] : -1e30f;
#pragma unroll
        for (int o = 4; o; o >>= 1) v = fmaxf(v, __shfl_xor_sync(0xffffffffu, v, o));
        if (tid == 0) red[0] = v;
    }
    __syncthreads();
    const float mm = red[0];
    __syncthreads();

    // pass 2: exp + sum
    float s = 0.0f;
    for (int i = tid * 4; i < n; i += 256 * 4) {
        float4 v = *(float4*)(row + i);
        v.x = __expf(v.x - mm);
        v.y = __expf(v.y - mm);
        v.z = __expf(v.z - mm);
        v.w = __expf(v.w - mm);
        s += v.x + v.y + v.z + v.w;
        *(float4*)(row + i) = v;
    }
#pragma unroll
    for (int o = 16; o; o >>= 1) s += __shfl_xor_sync(0xffffffffu, s, o);
    if ((tid & 31) == 0) red[tid >> 5] = s;
    __syncthreads();
    if (tid < 32) {
        float v = (tid < 8) ? red[tid] : 0.0f;
#pragma unroll
        for (int o = 4; o; o >>= 1) v += __shfl_xor_sync(0xffffffffu, v, o);
        if (tid == 0) red[0] = v;
    }
    __syncthreads();
    const float inv = 1.0f / red[0];

    // pass 3: normalize
    for (int i = tid * 4; i < n; i += 256 * 4) {
        float4 v = *(float4*)(row + i);
        v.x *= inv; v.y *= inv; v.z *= inv; v.w *= inv;
        *(float4*)(row + i) = v;
    }
}

extern "C" void kernel_launch(void* const* d_in, const int* in_sizes, int n_in,
                              void* d_out, int out_size)
{
    (void)in_sizes; (void)n_in; (void)out_size;
    const float* x  = (const float*)d_in[0];
    const float* Wk = (const float*)d_in[1];
    const float* Wq = (const float*)d_in[2];
    const float* Wv = (const float*)d_in[3];
    float* out = (float*)d_out;

    float *Q, *K, *V, *S;
    cudaGetSymbolAddress((void**)&Q, g_Q);
    cudaGetSymbolAddress((void**)&K, g_K);
    cudaGetSymbolAddress((void**)&V, g_V);
    cudaGetSymbolAddress((void**)&S, g_S);

    const int M_qkv = BATCH * SEQ;   // 8192
    const long sQKV = (long)SEQ * DIM;
    const long sS   = (long)SEQ * SEQ;

    // 1) QKV projections: Y = x @ W^T   (x:[8192,1024], W:[1024,1024])
    {
        dim3 grid(DIM / BN, M_qkv / BM, 1);
        gemm_nt<<<grid, NTHREADS>>>(x, Wk, K, M_qkv, DIM, DIM, 0, 0, 0, 1.0f);
        gemm_nt<<<grid, NTHREADS>>>(x, Wq, Q, M_qkv, DIM, DIM, 0, 0, 0, 1.0f);
        gemm_nt<<<grid, NTHREADS>>>(x, Wv, V, M_qkv, DIM, DIM, 0, 0, 0, 1.0f);
    }

    // 2) scores = (Q @ K^T) / sqrt(1024), per batch
    {
        dim3 grid(SEQ / BN, SEQ / BM, BATCH);
        gemm_nt<<<grid, NTHREADS>>>(Q, K, S, SEQ, SEQ, DIM,
                                    sQKV, sQKV, sS, 1.0f / 32.0f);
    }

    // 3) row softmax over 2048-length rows
    softmax_rows<<<BATCH * SEQ, 256>>>(S, SEQ);

    // 4) context = P @ V, written straight to d_out
    {
        dim3 grid(DIM / BN, SEQ / BM, BATCH);
        gemm_nn<<<grid, NTHREADS>>>(S, V, out, SEQ, DIM, SEQ,
                                    sS, sQKV, sQKV);
    }
}

// round 6
// speedup vs baseline: 3.3266x; 3.3266x over previous
#include <cuda_runtime.h>
#include <cstdint>
#include <math.h>

// Shapes fixed by reference
#define BATCH 4
#define SEQ   2048
#define DIM   1024

// ---------------- scratch (device globals; allocation-free rule) ------------
__device__ float g_Q [(long)BATCH * SEQ * DIM];   // [8192,1024]
__device__ float g_K [(long)BATCH * SEQ * DIM];   // [8192,1024]
__device__ float g_Vt[(long)BATCH * DIM * SEQ];   // per batch [1024,2048] (V^T)
__device__ float g_S [(long)BATCH * SEQ * SEQ];   // scores / probs
__device__ float g_xr[(long)BATCH * SEQ * DIM];   // x rounded to tf32
__device__ float g_Wr[3L * DIM * DIM];            // Wq,Wk,Wv rounded to tf32

// ---------------- helpers ----------------
__device__ __forceinline__ uint32_t smem_u32(const void* p) {
    uint32_t a;
    asm("{ .reg .u64 t; cvta.to.shared.u64 t, %1; cvt.u32.u64 %0, t; }" : "=r"(a) : "l"(p));
    return a;
}
__device__ __forceinline__ void cp_async16(uint32_t dst, const void* src) {
    asm volatile("cp.async.cg.shared.global [%0], [%1], 16;" :: "r"(dst), "l"(src));
}
#define CP_COMMIT() asm volatile("cp.async.commit_group;" ::: "memory")
#define CP_WAIT(n)  asm volatile("cp.async.wait_group %0;" :: "n"(n) : "memory")

__device__ __forceinline__ uint32_t round_tf32_bits(float f) {
    uint32_t u;
    asm("cvt.rna.tf32.f32 %0, %1;" : "=r"(u) : "f"(f));
    return u;
}
__device__ __forceinline__ float round_tf32(float f) {
    return __uint_as_float(round_tf32_bits(f));
}

// m16n8k8 tf32 MMA (legacy path — valid on plain compute_100 target)
__device__ __forceinline__ void mma_tf32(float* d, const uint32_t* a, const uint32_t* b) {
    asm volatile(
        "mma.sync.aligned.m16n8k8.row.col.f32.tf32.tf32.f32 "
        "{%0,%1,%2,%3}, {%4,%5,%6,%7}, {%8,%9}, {%0,%1,%2,%3};\n"
        : "+f"(d[0]), "+f"(d[1]), "+f"(d[2]), "+f"(d[3])
        : "r"(a[0]), "r"(a[1]), "r"(a[2]), "r"(a[3]), "r"(b[0]), "r"(b[1]));
}

// ---------------- tf32 mma.sync NT GEMM ----------------
// C[M,N] = alpha * A[M,K] @ B[N,K]^T, all row-major (K contiguous), fp32 data
// already rounded to tf32 bit patterns. Batched via blockIdx.z with strides.
// CTA tile 128x128, K tile 32, 3-stage cp.async pipeline, 8 warps (2x4).
#define BM 128
#define BN 128
#define BK 32
#define STAGES 3
#define ROWP 36                         // padded row stride (floats)
#define TILE_F (128 * ROWP)             // floats per (A or B) stage tile
#define SMEM_TOTAL (2 * STAGES * TILE_F * 4)   // 110,592 B

__global__ __launch_bounds__(256, 2)
void gemm_tc(const float* __restrict__ A, const float* __restrict__ B,
             float* __restrict__ C, int K, int N,
             long sA, long sB, long sC, float alpha, int round_out)
{
    extern __shared__ float smemf[];
    const uint32_t sbase = smem_u32(smemf);
    const int tid = threadIdx.x;
    const int wid = tid >> 5;
    const int lid = tid & 31;
    const int warpM = wid >> 2;          // 0..1  -> 64-row slab
    const int warpN = wid & 3;           // 0..3  -> 32-col slab
    const int qrow = lid >> 2;           // 0..7
    const int qcol = lid & 3;            // 0..3

    const char* Ab = (const char*)(A + (long)blockIdx.z * sA + (long)blockIdx.y * BM * K);
    const char* Bb = (const char*)(B + (long)blockIdx.z * sB + (long)blockIdx.x * BN * K);
    const long  Kb = (long)K * 4;
    const int   NK = K / BK;

    // loader: 128 rows x 8 chunks(16B) per tile = 1024 chunks;
    // chunk id = tid + j*256 -> row = cid>>3, col = (cid&7)*16
    auto load_tile = [&](int kt, int slot) {
        const uint32_t sa = sbase + slot * TILE_F * 4;
        const uint32_t sb = sbase + (STAGES + slot) * TILE_F * 4;
        const long kofs = (long)kt * BK * 4;
#pragma unroll
        for (int j = 0; j < 4; j++) {
            const int cid = tid + j * 256;
            const int r = cid >> 3;
            const int cc = (cid & 7) * 16;
            const uint32_t so = (uint32_t)(r * ROWP * 4 + cc);
            cp_async16(sa + so, Ab + (long)r * Kb + kofs + cc);
            cp_async16(sb + so, Bb + (long)r * Kb + kofs + cc);
        }
    };

    float acc[4][4][4];
#pragma unroll
    for (int mt = 0; mt < 4; mt++)
#pragma unroll
        for (int nt = 0; nt < 4; nt++)
#pragma unroll
            for (int i = 0; i < 4; i++) acc[mt][nt][i] = 0.0f;

#pragma unroll
    for (int s = 0; s < STAGES - 1; s++) { load_tile(s, s); CP_COMMIT(); }

    for (int kt = 0; kt < NK; kt++) {
        const int slot = kt % STAGES;
        CP_WAIT(STAGES - 2);
        __syncthreads();

        const int pf = kt + STAGES - 1;
        if (pf < NK) load_tile(pf, pf % STAGES);
        CP_COMMIT();

        const float* As = smemf + slot * TILE_F;
        const float* Bs = smemf + (STAGES + slot) * TILE_F;
#pragma unroll
        for (int ks = 0; ks < BK / 8; ks++) {
            const int k = ks * 8 + qcol;
            uint32_t a[4][4], b[4][2];
#pragma unroll
            for (int mt = 0; mt < 4; mt++) {
                const int r = warpM * 64 + mt * 16 + qrow;
                a[mt][0] = __float_as_uint(As[r * ROWP + k]);
                a[mt][1] = __float_as_uint(As[(r + 8) * ROWP + k]);
                a[mt][2] = __float_as_uint(As[r * ROWP + k + 4]);
                a[mt][3] = __float_as_uint(As[(r + 8) * ROWP + k + 4]);
            }
#pragma unroll
            for (int nt = 0; nt < 4; nt++) {
                const int c = warpN * 32 + nt * 8 + qrow;
                b[nt][0] = __float_as_uint(Bs[c * ROWP + k]);
                b[nt][1] = __float_as_uint(Bs[c * ROWP + k + 4]);
            }
#pragma unroll
            for (int mt = 0; mt < 4; mt++)
#pragma unroll
                for (int nt = 0; nt < 4; nt++)
                    mma_tf32(acc[mt][nt], a[mt], b[nt]);
        }
        // next iteration's __syncthreads() protects slot reuse
    }

    // epilogue: c0,c1 at (row, col), c2,c3 at (row+8, col); col base = 2*qcol
    float* Cb = C + (long)blockIdx.z * sC;
#pragma unroll
    for (int mt = 0; mt < 4; mt++) {
        const long r0 = (long)blockIdx.y * BM + warpM * 64 + mt * 16 + qrow;
#pragma unroll
        for (int nt = 0; nt < 4; nt++) {
            const long c0 = (long)blockIdx.x * BN + warpN * 32 + nt * 8 + qcol * 2;
            float2 lo, hi;
            lo.x = acc[mt][nt][0] * alpha; lo.y = acc[mt][nt][1] * alpha;
            hi.x = acc[mt][nt][2] * alpha; hi.y = acc[mt][nt][3] * alpha;
            if (round_out) {
                lo.x = round_tf32(lo.x); lo.y = round_tf32(lo.y);
                hi.x = round_tf32(hi.x); hi.y = round_tf32(hi.y);
            }
            *(float2*)(Cb + r0 * N + c0)       = lo;
            *(float2*)(Cb + (r0 + 8) * N + c0) = hi;
        }
    }
}

// ---------------- tf32 rounding (RNA) copy ----------------
__global__ __launch_bounds__(256)
void round_copy_tf32(const float* __restrict__ in, float* __restrict__ out)
{
    const long i = ((long)blockIdx.x * 256 + threadIdx.x) * 4;
    float4 v = *(const float4*)(in + i);
    v.x = round_tf32(v.x); v.y = round_tf32(v.y);
    v.z = round_tf32(v.z); v.w = round_tf32(v.w);
    *(float4*)(out + i) = v;
}

// ---------------- row softmax (2048-wide rows), rounds P to tf32 ------------
__global__ __launch_bounds__(256)
void softmax_rows(float* __restrict__ S, int n)
{
    float* row = S + (long)blockIdx.x * n;
    const int tid = threadIdx.x;
    __shared__ float red[8];

    float m = -1e30f;
    for (int i = tid * 4; i < n; i += 1024) {
        float4 v = *(const float4*)(row + i);
        m = fmaxf(m, fmaxf(fmaxf(v.x, v.y), fmaxf(v.z, v.w)));
    }
#pragma unroll
    for (int o = 16; o; o >>= 1) m = fmaxf(m, __shfl_xor_sync(0xffffffffu, m, o));
    if ((tid & 31) == 0) red[tid >> 5] = m;
    __syncthreads();
    if (tid < 32) {
        float v = (tid < 8) ? red[tid] : -1e30f;
#pragma unroll
        for (int o = 4; o; o >>= 1) v = fmaxf(v, __shfl_xor_sync(0xffffffffu, v, o));
        if (tid == 0) red[0] = v;
    }
    __syncthreads();
    const float mm = red[0];
    __syncthreads();

    float s = 0.0f;
    for (int i = tid * 4; i < n; i += 1024) {
        float4 v = *(float4*)(row + i);
        v.x = __expf(v.x - mm);
        v.y = __expf(v.y - mm);
        v.z = __expf(v.z - mm);
        v.w = __expf(v.w - mm);
        s += v.x + v.y + v.z + v.w;
        *(float4*)(row + i) = v;
    }
#pragma unroll
    for (int o = 16; o; o >>= 1) s += __shfl_xor_sync(0xffffffffu, s, o);
    if ((tid & 31) == 0) red[tid >> 5] = s;
    __syncthreads();
    if (tid < 32) {
        float v = (tid < 8) ? red[tid] : 0.0f;
#pragma unroll
        for (int o = 4; o; o >>= 1) v += __shfl_xor_sync(0xffffffffu, v, o);
        if (tid == 0) red[0] = v;
    }
    __syncthreads();
    const float inv = 1.0f / red[0];

    for (int i = tid * 4; i < n; i += 1024) {
        float4 v = *(float4*)(row + i);
        v.x = round_tf32(v.x * inv);
        v.y = round_tf32(v.y * inv);
        v.z = round_tf32(v.z * inv);
        v.w = round_tf32(v.w * inv);
        *(float4*)(row + i) = v;
    }
}

// ---------------- launcher ----------------
extern "C" void kernel_launch(void* const* d_in, const int* in_sizes, int n_in,
                              void* d_out, int out_size)
{
    (void)in_sizes; (void)n_in; (void)out_size;
    const float* x  = (const float*)d_in[0];
    const float* Wk = (const float*)d_in[1];
    const float* Wq = (const float*)d_in[2];
    const float* Wv = (const float*)d_in[3];
    float* out = (float*)d_out;

    float *Q, *Kp, *Vt, *S, *xr, *Wr;
    cudaGetSymbolAddress((void**)&Q,  g_Q);
    cudaGetSymbolAddress((void**)&Kp, g_K);
    cudaGetSymbolAddress((void**)&Vt, g_Vt);
    cudaGetSymbolAddress((void**)&S,  g_S);
    cudaGetSymbolAddress((void**)&xr, g_xr);
    cudaGetSymbolAddress((void**)&Wr, g_Wr);

    cudaFuncSetAttribute(gemm_tc, cudaFuncAttributeMaxDynamicSharedMemorySize, SMEM_TOTAL);

    const long nX = (long)BATCH * SEQ * DIM;
    const long nW = (long)DIM * DIM;
    float* Wq_r = Wr + 0 * nW;
    float* Wk_r = Wr + 1 * nW;
    float* Wv_r = Wr + 2 * nW;

    // 0) round inputs to tf32 (RNA) so MMA register reads are exact
    round_copy_tf32<<<(int)(nX / 1024), 256>>>(x,  xr);
    round_copy_tf32<<<(int)(nW / 1024), 256>>>(Wq, Wq_r);
    round_copy_tf32<<<(int)(nW / 1024), 256>>>(Wk, Wk_r);
    round_copy_tf32<<<(int)(nW / 1024), 256>>>(Wv, Wv_r);

    const long sX = (long)SEQ * DIM;
    const long sS = (long)SEQ * SEQ;
    const long sV = (long)DIM * SEQ;

    // 1) Q = x @ Wq^T, K = x @ Wk^T   (M=8192, N=1024, K=1024)
    {
        dim3 g(DIM / BN, (BATCH * SEQ) / BM, 1);
        gemm_tc<<<g, 256, SMEM_TOTAL>>>(xr, Wq_r, Q,  DIM, DIM, 0, 0, 0, 1.0f, 1);
        gemm_tc<<<g, 256, SMEM_TOTAL>>>(xr, Wk_r, Kp, DIM, DIM, 0, 0, 0, 1.0f, 1);
    }
    // 2) Vt[b] = Wv @ x[b]^T          (M=1024, N=2048, K=1024, batched)
    {
        dim3 g(SEQ / BN, DIM / BM, BATCH);
        gemm_tc<<<g, 256, SMEM_TOTAL>>>(Wv_r, xr, Vt, DIM, SEQ, 0, sX, sV, 1.0f, 1);
    }
    // 3) S[b] = (Q[b] @ K[b]^T) / 32  (M=2048, N=2048, K=1024, batched)
    {
        dim3 g(SEQ / BN, SEQ / BM, BATCH);
        gemm_tc<<<g, 256, SMEM_TOTAL>>>(Q, Kp, S, DIM, SEQ, sX, sX, sS, 1.0f / 32.0f, 1);
    }
    // 4) row softmax (writes tf32-rounded P)
    softmax_rows<<<BATCH * SEQ, 256>>>(S, SEQ);

    // 5) out[b] = P[b] @ Vt[b]^T      (M=2048, N=1024, K=2048, batched)
    {
        dim3 g(DIM / BN, SEQ / BM, BATCH);
        gemm_tc<<<g, 256, SMEM_TOTAL>>>(S, Vt, out, SEQ, DIM, sS, sV, sX, 1.0f, 0);
    }
}

// round 8
// speedup vs baseline: 6.0230x; 1.8106x over previous
#include <cuda_runtime.h>
#include <cuda_fp16.h>
#include <cstdint>
#include <math.h>

// Shapes fixed by reference
#define BATCH 4
#define SEQ   2048
#define DIM   1024

// ---------------- scratch (device globals; allocation-free rule) ------------
__device__ __half g_Qh [(long)BATCH * SEQ * DIM];   // [8192,1024]
__device__ __half g_Kh [(long)BATCH * SEQ * DIM];   // [8192,1024]
__device__ __half g_Vth[(long)BATCH * DIM * SEQ];   // per batch [1024,2048] (V^T)
__device__ float  g_S  [(long)BATCH * SEQ * SEQ];   // scores (fp32)
__device__ __half g_P  [(long)BATCH * SEQ * SEQ];   // softmax probs (fp16)
__device__ __half g_xh [(long)BATCH * SEQ * DIM];   // x in fp16
__device__ __half g_Wh [3L * DIM * DIM];            // Wq,Wk,Wv in fp16

// ---------------- helpers ----------------
__device__ __forceinline__ uint32_t smem_u32(const void* p) {
    uint32_t a;
    asm("{ .reg .u64 t; cvta.to.shared.u64 t, %1; cvt.u32.u64 %0, t; }" : "=r"(a) : "l"(p));
    return a;
}
__device__ __forceinline__ void cp_async16(uint32_t dst, const void* src) {
    asm volatile("cp.async.cg.shared.global [%0], [%1], 16;" :: "r"(dst), "l"(src));
}
#define CP_COMMIT() asm volatile("cp.async.commit_group;" ::: "memory")
#define CP_WAIT(n)  asm volatile("cp.async.wait_group %0;" :: "n"(n) : "memory")

// m16n8k16 fp16 MMA, f32 accumulate (valid on plain compute_100 target)
__device__ __forceinline__ void mma_f16(float* d, const uint32_t* a, const uint32_t* b) {
    asm volatile(
        "mma.sync.aligned.m16n8k16.row.col.f32.f16.f16.f32 "
        "{%0,%1,%2,%3}, {%4,%5,%6,%7}, {%8,%9}, {%0,%1,%2,%3};\n"
        : "+f"(d[0]), "+f"(d[1]), "+f"(d[2]), "+f"(d[3])
        : "r"(a[0]), "r"(a[1]), "r"(a[2]), "r"(a[3]), "r"(b[0]), "r"(b[1]));
}

// ---------------- fp16 mma.sync NT GEMM ----------------
// C[M,N] = alpha * A[M,K] @ B[N,K]^T; A,B fp16 row-major (K contiguous).
// Batched via blockIdx.z (strides in elements). CTA tile 128x128, K tile 64
// halves (128B rows), 3-stage cp.async pipeline, 8 warps (2x4).
#define BM 128
#define BN 128
#define BKH 64                           // K-tile in halves (128 bytes)
#define STAGES 3
#define ROWB 144                         // padded row stride in bytes (128+16)
#define TILE_B (128 * ROWB)              // bytes per stage tile (18432)
#define SMEM_TOTAL (2 * STAGES * TILE_B) // 110,592 B

__global__ __launch_bounds__(256, 2)
void gemm_hf(const __half* __restrict__ A, const __half* __restrict__ B,
             void* __restrict__ C, int K, int N,
             long sA, long sB, long sC, float alpha, int out_half)
{
    extern __shared__ char smem[];
    const uint32_t sbase = smem_u32(smem);
    const int tid = threadIdx.x;
    const int wid = tid >> 5;
    const int lid = tid & 31;
    const int warpM = wid >> 2;          // 0..1  -> 64-row slab
    const int warpN = wid & 3;           // 0..3  -> 32-col slab
    const int qrow = lid >> 2;           // 0..7
    const int qcol = lid & 3;            // 0..3

    const char* Ab = (const char*)(A + (long)blockIdx.z * sA + (long)blockIdx.y * BM * K);
    const char* Bb = (const char*)(B + (long)blockIdx.z * sB + (long)blockIdx.x * BN * K);
    const long  Kb = (long)K * 2;        // row pitch bytes
    const int   NK = K / BKH;

    // loader: 128 rows x 8 chunks(16B) per tile; cid = tid + j*256
    auto load_tile = [&](int kt, int slot) {
        const uint32_t sa = sbase + slot * TILE_B;
        const uint32_t sb = sbase + (STAGES + slot) * TILE_B;
        const long kofs = (long)kt * 128;             // 64 halves = 128B
#pragma unroll
        for (int j = 0; j < 4; j++) {
            const int cid = tid + j * 256;
            const int r  = cid >> 3;
            const int cc = (cid & 7) * 16;
            const uint32_t so = (uint32_t)(r * ROWB + cc);
            cp_async16(sa + so, Ab + (long)r * Kb + kofs + cc);
            cp_async16(sb + so, Bb + (long)r * Kb + kofs + cc);
        }
    };

    float acc[4][4][4];
#pragma unroll
    for (int mt = 0; mt < 4; mt++)
#pragma unroll
        for (int nt = 0; nt < 4; nt++)
#pragma unroll
            for (int i = 0; i < 4; i++) acc[mt][nt][i] = 0.0f;

#pragma unroll
    for (int s = 0; s < STAGES - 1; s++) { load_tile(s, s); CP_COMMIT(); }

    for (int kt = 0; kt < NK; kt++) {
        const int slot = kt % STAGES;
        CP_WAIT(STAGES - 2);
        __syncthreads();

        const int pf = kt + STAGES - 1;
        if (pf < NK) load_tile(pf, pf % STAGES);
        CP_COMMIT();

        const char* As = smem + slot * TILE_B;
        const char* Bs = smem + (STAGES + slot) * TILE_B;
#pragma unroll
        for (int ks = 0; ks < BKH / 16; ks++) {
            const int kb = ks * 32 + qcol * 4;        // byte offset of k pair
            uint32_t a[4][4], b[4][2];
#pragma unroll
            for (int mt = 0; mt < 4; mt++) {
                const int r = warpM * 64 + mt * 16 + qrow;
                const char* p0 = As + r * ROWB + kb;
                const char* p1 = As + (r + 8) * ROWB + kb;
                a[mt][0] = *(const uint32_t*)(p0);
                a[mt][1] = *(const uint32_t*)(p1);
                a[mt][2] = *(const uint32_t*)(p0 + 16);   // k+8 halves
                a[mt][3] = *(const uint32_t*)(p1 + 16);
            }
#pragma unroll
            for (int nt = 0; nt < 4; nt++) {
                const int c = warpN * 32 + nt * 8 + qrow;
                const char* p = Bs + c * ROWB + kb;
                b[nt][0] = *(const uint32_t*)(p);
                b[nt][1] = *(const uint32_t*)(p + 16);
            }
#pragma unroll
            for (int mt = 0; mt < 4; mt++)
#pragma unroll
                for (int nt = 0; nt < 4; nt++)
                    mma_f16(acc[mt][nt], a[mt], b[nt]);
        }
        // next iteration's __syncthreads() protects slot reuse
    }

    // epilogue: c0,c1 at (row, col..col+1), c2,c3 at (row+8, ...)
#pragma unroll
    for (int mt = 0; mt < 4; mt++) {
        const long r0 = (long)blockIdx.y * BM + warpM * 64 + mt * 16 + qrow;
#pragma unroll
        for (int nt = 0; nt < 4; nt++) {
            const long c0 = (long)blockIdx.x * BN + warpN * 32 + nt * 8 + qcol * 2;
            float lo0 = acc[mt][nt][0] * alpha, lo1 = acc[mt][nt][1] * alpha;
            float hi0 = acc[mt][nt][2] * alpha, hi1 = acc[mt][nt][3] * alpha;
            if (out_half) {
                __half* Cb = (__half*)C + (long)blockIdx.z * sC;
                *(__half2*)(Cb + r0 * N + c0)       = __floats2half2_rn(lo0, lo1);
                *(__half2*)(Cb + (r0 + 8) * N + c0) = __floats2half2_rn(hi0, hi1);
            } else {
                float* Cb = (float*)C + (long)blockIdx.z * sC;
                float2 lo; lo.x = lo0; lo.y = lo1;
                float2 hi; hi.x = hi0; hi.y = hi1;
                *(float2*)(Cb + r0 * N + c0)       = lo;
                *(float2*)(Cb + (r0 + 8) * N + c0) = hi;
            }
        }
    }
}

// ---------------- f32 -> f16 convert ----------------
__global__ __launch_bounds__(256)
void convert_f16(const float* __restrict__ in, __half* __restrict__ out)
{
    const long i = ((long)blockIdx.x * 256 + threadIdx.x) * 4;
    float4 v = *(const float4*)(in + i);
    __half2 h0 = __floats2half2_rn(v.x, v.y);
    __half2 h1 = __floats2half2_rn(v.z, v.w);
    uint2 u;
    u.x = *(uint32_t*)&h0;
    u.y = *(uint32_t*)&h1;
    *(uint2*)(out + i) = u;
}

// ---------------- row softmax: fp32 scores in, fp16 probs out ---------------
__global__ __launch_bounds__(256)
void softmax_rows(const float* __restrict__ S, __half* __restrict__ P, int n)
{
    const float* row = S + (long)blockIdx.x * n;
    __half* prow = P + (long)blockIdx.x * n;
    const int tid = threadIdx.x;
    __shared__ float red[8];
    __shared__ float sm, ssum;

    float m = -1e30f;
    for (int i = tid * 4; i < n; i += 1024) {
        float4 v = *(const float4*)(row + i);
        m = fmaxf(m, fmaxf(fmaxf(v.x, v.y), fmaxf(v.z, v.w)));
    }
#pragma unroll
    for (int o = 16; o; o >>= 1) m = fmaxf(m, __shfl_xor_sync(0xffffffffu, m, o));
    if ((tid & 31) == 0) red[tid >> 5] = m;
    __syncthreads();
    if (tid < 32) {
        float v = (tid < 8) ? red[tid] : -1e30f;
#pragma unroll
        for (int o = 4; o; o >>= 1) v = fmaxf(v, __shfl_xor_sync(0xffffffffu, v, o));
        if (tid == 0) sm = v;
    }
    __syncthreads();
    const float mm = sm;

    float s = 0.0f;
    for (int i = tid * 4; i < n; i += 1024) {
        float4 v = *(const float4*)(row + i);
        s += __expf(v.x - mm) + __expf(v.y - mm) + __expf(v.z - mm) + __expf(v.w - mm);
    }
#pragma unroll
    for (int o = 16; o; o >>= 1) s += __shfl_xor_sync(0xffffffffu, s, o);
    if ((tid & 31) == 0) red[tid >> 5] = s;
    __syncthreads();
    if (tid < 32) {
        float v = (tid < 8) ? red[tid] : 0.0f;
#pragma unroll
        for (int o = 4; o; o >>= 1) v += __shfl_xor_sync(0xffffffffu, v, o);
        if (tid == 0) ssum = v;
    }
    __syncthreads();
    const float inv = 1.0f / ssum;

    for (int i = tid * 4; i < n; i += 1024) {
        float4 v = *(const float4*)(row + i);
        __half2 h0 = __floats2half2_rn(__expf(v.x - mm) * inv, __expf(v.y - mm) * inv);
        __half2 h1 = __floats2half2_rn(__expf(v.z - mm) * inv, __expf(v.w - mm) * inv);
        uint2 u;
        u.x = *(uint32_t*)&h0;
        u.y = *(uint32_t*)&h1;
        *(uint2*)(prow + i) = u;
    }
}

// ---------------- launcher ----------------
extern "C" void kernel_launch(void* const* d_in, const int* in_sizes, int n_in,
                              void* d_out, int out_size)
{
    (void)in_sizes; (void)n_in; (void)out_size;
    const float* x  = (const float*)d_in[0];
    const float* Wk = (const float*)d_in[1];
    const float* Wq = (const float*)d_in[2];
    const float* Wv = (const float*)d_in[3];
    float* out = (float*)d_out;

    __half *Qh, *Kh, *Vth, *P, *xh, *Wh;
    float *S;
    cudaGetSymbolAddress((void**)&Qh,  g_Qh);
    cudaGetSymbolAddress((void**)&Kh,  g_Kh);
    cudaGetSymbolAddress((void**)&Vth, g_Vth);
    cudaGetSymbolAddress((void**)&S,   g_S);
    cudaGetSymbolAddress((void**)&P,   g_P);
    cudaGetSymbolAddress((void**)&xh,  g_xh);
    cudaGetSymbolAddress((void**)&Wh,  g_Wh);

    cudaFuncSetAttribute(gemm_hf, cudaFuncAttributeMaxDynamicSharedMemorySize, SMEM_TOTAL);

    const long nX = (long)BATCH * SEQ * DIM;
    const long nW = (long)DIM * DIM;
    __half* Wq_h = Wh + 0 * nW;
    __half* Wk_h = Wh + 1 * nW;
    __half* Wv_h = Wh + 2 * nW;

    // 0) convert inputs to fp16
    convert_f16<<<(int)(nX / 1024), 256>>>(x,  xh);
    convert_f16<<<(int)(nW / 1024), 256>>>(Wq, Wq_h);
    convert_f16<<<(int)(nW / 1024), 256>>>(Wk, Wk_h);
    convert_f16<<<(int)(nW / 1024), 256>>>(Wv, Wv_h);

    const long sX = (long)SEQ * DIM;
    const long sS = (long)SEQ * SEQ;
    const long sV = (long)DIM * SEQ;

    // 1) Q = x @ Wq^T, K = x @ Wk^T   (M=8192, N=1024, K=1024) -> fp16
    {
        dim3 g(DIM / BN, (BATCH * SEQ) / BM, 1);
        gemm_hf<<<g, 256, SMEM_TOTAL>>>(xh, Wq_h, Qh, DIM, DIM, 0, 0, 0, 1.0f, 1);
        gemm_hf<<<g, 256, SMEM_TOTAL>>>(xh, Wk_h, Kh, DIM, DIM, 0, 0, 0, 1.0f, 1);
    }
    // 2) Vt[b] = Wv @ x[b]^T          (M=1024, N=2048, K=1024) -> fp16
    {
        dim3 g(SEQ / BN, DIM / BM, BATCH);
        gemm_hf<<<g, 256, SMEM_TOTAL>>>(Wv_h, xh, Vth, DIM, SEQ, 0, sX, sV, 1.0f, 1);
    }
    // 3) S[b] = (Q[b] @ K[b]^T) / 32  (M=2048, N=2048, K=1024) -> fp32
    {
        dim3 g(SEQ / BN, SEQ / BM, BATCH);
        gemm_hf<<<g, 256, SMEM_TOTAL>>>(Qh, Kh, S, DIM, SEQ, sX, sX, sS, 1.0f / 32.0f, 0);
    }
    // 4) row softmax -> fp16 probs
    softmax_rows<<<BATCH * SEQ, 256>>>(S, P, SEQ);

    // 5) out[b] = P[b] @ Vt[b]^T      (M=2048, N=1024, K=2048) -> fp32 d_out
    {
        dim3 g(DIM / BN, SEQ / BM, BATCH);
        gemm_hf<<<g, 256, SMEM_TOTAL>>>(P, Vth, out, SEQ, DIM, sS, sV, sX, 1.0f, 0);
    }
}

// round 9
// speedup vs baseline: 6.4621x; 1.0729x over previous
#include <cuda_runtime.h>
#include <cuda_fp16.h>
#include <cstdint>
#include <math.h>

// Shapes fixed by reference
#define BATCH 4
#define SEQ   2048
#define DIM   1024

// ---------------- scratch (device globals; allocation-free rule) ------------
__device__ __half g_Qh [(long)BATCH * SEQ * DIM];   // [8192,1024]
__device__ __half g_Kh [(long)BATCH * SEQ * DIM];   // [8192,1024]
__device__ __half g_Vth[(long)BATCH * DIM * SEQ];   // per batch [1024,2048] (V^T)
__device__ float  g_S  [(long)BATCH * SEQ * SEQ];   // scores (fp32)
__device__ __half g_P  [(long)BATCH * SEQ * SEQ];   // softmax probs (fp16)
__device__ __half g_xh [(long)BATCH * SEQ * DIM];   // x in fp16
__device__ __half g_Wh [3L * DIM * DIM];            // Wq,Wk,Wv in fp16

// ---------------- helpers ----------------
__device__ __forceinline__ uint32_t smem_u32(const void* p) {
    uint32_t a;
    asm("{ .reg .u64 t; cvta.to.shared.u64 t, %1; cvt.u32.u64 %0, t; }" : "=r"(a) : "l"(p));
    return a;
}
__device__ __forceinline__ void cp_async16(uint32_t dst, const void* src) {
    asm volatile("cp.async.cg.shared.global [%0], [%1], 16;" :: "r"(dst), "l"(src));
}
#define CP_COMMIT() asm volatile("cp.async.commit_group;" ::: "memory")
#define CP_WAIT(n)  asm volatile("cp.async.wait_group %0;" :: "n"(n) : "memory")

// m16n8k16 fp16 MMA, f32 accumulate (valid on plain compute_100 target)
__device__ __forceinline__ void mma_f16(float* d, const uint32_t* a, const uint32_t* b) {
    asm volatile(
        "mma.sync.aligned.m16n8k16.row.col.f32.f16.f16.f32 "
        "{%0,%1,%2,%3}, {%4,%5,%6,%7}, {%8,%9}, {%0,%1,%2,%3};\n"
        : "+f"(d[0]), "+f"(d[1]), "+f"(d[2]), "+f"(d[3])
        : "r"(a[0]), "r"(a[1]), "r"(a[2]), "r"(a[3]), "r"(b[0]), "r"(b[1]));
}
__device__ __forceinline__ void ldsm_x4(uint32_t* r, uint32_t addr) {
    asm volatile("ldmatrix.sync.aligned.m8n8.x4.shared.b16 {%0,%1,%2,%3}, [%4];"
                 : "=r"(r[0]), "=r"(r[1]), "=r"(r[2]), "=r"(r[3]) : "r"(addr));
}

// ---------------- fp16 mma.sync NT GEMM (ldmatrix fragments) ----------------
// C[M,N] = alpha * A[M,K] @ B[N,K]^T; A,B fp16 row-major (K contiguous).
// Batched via blockIdx.z (strides in elements). CTA tile 128x128, K tile 64
// halves (128B rows), 3-stage cp.async pipeline, 8 warps (2x4).
#define BM 128
#define BN 128
#define BKH 64                           // K-tile in halves (128 bytes)
#define STAGES 3
#define ROWB 144                         // padded row stride in bytes (128+16)
#define TILE_B (128 * ROWB)              // bytes per stage tile (18432)
#define SMEM_TOTAL (2 * STAGES * TILE_B) // 110,592 B

__global__ __launch_bounds__(256, 2)
void gemm_hf(const __half* __restrict__ A, const __half* __restrict__ B,
             void* __restrict__ C, int K, int N,
             long sA, long sB, long sC, float alpha, int out_half)
{
    extern __shared__ char smem[];
    const uint32_t sbase = smem_u32(smem);
    const int tid = threadIdx.x;
    const int wid = tid >> 5;
    const int lid = tid & 31;
    const int warpM = wid >> 2;          // 0..1  -> 64-row slab
    const int warpN = wid & 3;           // 0..3  -> 32-col slab
    const int qrow = lid >> 2;           // 0..7
    const int qcol = lid & 3;            // 0..3

    const char* Ab = (const char*)(A + (long)blockIdx.z * sA + (long)blockIdx.y * BM * K);
    const char* Bb = (const char*)(B + (long)blockIdx.z * sB + (long)blockIdx.x * BN * K);
    const long  Kb = (long)K * 2;        // row pitch bytes
    const int   NK = K / BKH;

    // ldmatrix per-thread address offsets (within a stage tile), excluding ks:
    // A x4 tile mt: matrices {r0-7,k0-7},{r8-15,k0-7},{r0-7,k8-15},{r8-15,k8-15}
    //   lane -> row = warpM*64 + mt*16 + (lid&15), colByte = (lid>>4)*16
    uint32_t aoff[4];
#pragma unroll
    for (int mt = 0; mt < 4; mt++)
        aoff[mt] = (uint32_t)((warpM * 64 + mt * 16 + (lid & 15)) * ROWB + (lid >> 4) * 16);
    // B x4 pair p: matrices {n0-7,k0-7},{n0-7,k8-15},{n8-15,k0-7},{n8-15,k8-15}
    //   lane -> n = warpN*32 + p*16 + (lid>>4)*8 + (lid&7), colByte = ((lid>>3)&1)*16
    uint32_t boff[2];
#pragma unroll
    for (int p = 0; p < 2; p++)
        boff[p] = (uint32_t)((warpN * 32 + p * 16 + (lid >> 4) * 8 + (lid & 7)) * ROWB
                             + ((lid >> 3) & 1) * 16);

    // loader: 128 rows x 8 chunks(16B) per tile; cid = tid + j*256
    auto load_tile = [&](int kt, int slot) {
        const uint32_t sa = sbase + slot * TILE_B;
        const uint32_t sb = sbase + (STAGES + slot) * TILE_B;
        const long kofs = (long)kt * 128;             // 64 halves = 128B
#pragma unroll
        for (int j = 0; j < 4; j++) {
            const int cid = tid + j * 256;
            const int r  = cid >> 3;
            const int cc = (cid & 7) * 16;
            const uint32_t so = (uint32_t)(r * ROWB + cc);
            cp_async16(sa + so, Ab + (long)r * Kb + kofs + cc);
            cp_async16(sb + so, Bb + (long)r * Kb + kofs + cc);
        }
    };

    float acc[4][4][4];
#pragma unroll
    for (int mt = 0; mt < 4; mt++)
#pragma unroll
        for (int nt = 0; nt < 4; nt++)
#pragma unroll
            for (int i = 0; i < 4; i++) acc[mt][nt][i] = 0.0f;

#pragma unroll
    for (int s = 0; s < STAGES - 1; s++) { load_tile(s, s); CP_COMMIT(); }

    for (int kt = 0; kt < NK; kt++) {
        const int slot = kt % STAGES;
        CP_WAIT(STAGES - 2);
        __syncthreads();

        const int pf = kt + STAGES - 1;
        if (pf < NK) load_tile(pf, pf % STAGES);
        CP_COMMIT();

        const uint32_t As = sbase + slot * TILE_B;
        const uint32_t Bs = sbase + (STAGES + slot) * TILE_B;
#pragma unroll
        for (int ks = 0; ks < BKH / 16; ks++) {
            const uint32_t kb = ks * 32;              // 16 halves = 32 bytes
            uint32_t a[4][4], b[2][4];                // b[p] = {b[2p][0],b[2p][1],b[2p+1][0],b[2p+1][1]}
#pragma unroll
            for (int mt = 0; mt < 4; mt++) ldsm_x4(a[mt], As + aoff[mt] + kb);
#pragma unroll
            for (int p = 0; p < 2; p++)   ldsm_x4(b[p], Bs + boff[p] + kb);
#pragma unroll
            for (int mt = 0; mt < 4; mt++)
#pragma unroll
                for (int nt = 0; nt < 4; nt++)
                    mma_f16(acc[mt][nt], a[mt], &b[nt >> 1][(nt & 1) * 2]);
        }
        // next iteration's __syncthreads() protects slot reuse
    }

    // epilogue: c0,c1 at (row, col..col+1), c2,c3 at (row+8, ...)
#pragma unroll
    for (int mt = 0; mt < 4; mt++) {
        const long r0 = (long)blockIdx.y * BM + warpM * 64 + mt * 16 + qrow;
#pragma unroll
        for (int nt = 0; nt < 4; nt++) {
            const long c0 = (long)blockIdx.x * BN + warpN * 32 + nt * 8 + qcol * 2;
            float lo0 = acc[mt][nt][0] * alpha, lo1 = acc[mt][nt][1] * alpha;
            float hi0 = acc[mt][nt][2] * alpha, hi1 = acc[mt][nt][3] * alpha;
            if (out_half) {
                __half* Cb = (__half*)C + (long)blockIdx.z * sC;
                *(__half2*)(Cb + r0 * N + c0)       = __floats2half2_rn(lo0, lo1);
                *(__half2*)(Cb + (r0 + 8) * N + c0) = __floats2half2_rn(hi0, hi1);
            } else {
                float* Cb = (float*)C + (long)blockIdx.z * sC;
                float2 lo; lo.x = lo0; lo.y = lo1;
                float2 hi; hi.x = hi0; hi.y = hi1;
                *(float2*)(Cb + r0 * N + c0)       = lo;
                *(float2*)(Cb + (r0 + 8) * N + c0) = hi;
            }
        }
    }
}

// ---------------- f32 -> f16 convert ----------------
__global__ __launch_bounds__(256)
void convert_f16(const float* __restrict__ in, __half* __restrict__ out)
{
    const long i = ((long)blockIdx.x * 256 + threadIdx.x) * 4;
    float4 v = *(const float4*)(in + i);
    __half2 h0 = __floats2half2_rn(v.x, v.y);
    __half2 h1 = __floats2half2_rn(v.z, v.w);
    uint2 u;
    u.x = *(uint32_t*)&h0;
    u.y = *(uint32_t*)&h1;
    *(uint2*)(out + i) = u;
}

// ---------------- row softmax: fp32 scores in, fp16 probs out ---------------
__global__ __launch_bounds__(256)
void softmax_rows(const float* __restrict__ S, __half* __restrict__ P, int n)
{
    const float* row = S + (long)blockIdx.x * n;
    __half* prow = P + (long)blockIdx.x * n;
    const int tid = threadIdx.x;
    __shared__ float red[8];
    __shared__ float sm, ssum;

    float m = -1e30f;
    for (int i = tid * 4; i < n; i += 1024) {
        float4 v = *(const float4*)(row + i);
        m = fmaxf(m, fmaxf(fmaxf(v.x, v.y), fmaxf(v.z, v.w)));
    }
#pragma unroll
    for (int o = 16; o; o >>= 1) m = fmaxf(m, __shfl_xor_sync(0xffffffffu, m, o));
    if ((tid & 31) == 0) red[tid >> 5] = m;
    __syncthreads();
    if (tid < 32) {
        float v = (tid < 8) ? red[tid] : -1e30f;
#pragma unroll
        for (int o = 4; o; o >>= 1) v = fmaxf(v, __shfl_xor_sync(0xffffffffu, v, o));
        if (tid == 0) sm = v;
    }
    __syncthreads();
    const float mm = sm;

    float s = 0.0f;
    for (int i = tid * 4; i < n; i += 1024) {
        float4 v = *(const float4*)(row + i);
        s += __expf(v.x - mm) + __expf(v.y - mm) + __expf(v.z - mm) + __expf(v.w - mm);
    }
#pragma unroll
    for (int o = 16; o; o >>= 1) s += __shfl_xor_sync(0xffffffffu, s, o);
    if ((tid & 31) == 0) red[tid >> 5] = s;
    __syncthreads();
    if (tid < 32) {
        float v = (tid < 8) ? red[tid] : 0.0f;
#pragma unroll
        for (int o = 4; o; o >>= 1) v += __shfl_xor_sync(0xffffffffu, v, o);
        if (tid == 0) ssum = v;
    }
    __syncthreads();
    const float inv = 1.0f / ssum;

    for (int i = tid * 4; i < n; i += 1024) {
        float4 v = *(const float4*)(row + i);
        __half2 h0 = __floats2half2_rn(__expf(v.x - mm) * inv, __expf(v.y - mm) * inv);
        __half2 h1 = __floats2half2_rn(__expf(v.z - mm) * inv, __expf(v.w - mm) * inv);
        uint2 u;
        u.x = *(uint32_t*)&h0;
        u.y = *(uint32_t*)&h1;
        *(uint2*)(prow + i) = u;
    }
}

// ---------------- launcher ----------------
extern "C" void kernel_launch(void* const* d_in, const int* in_sizes, int n_in,
                              void* d_out, int out_size)
{
    (void)in_sizes; (void)n_in; (void)out_size;
    const float* x  = (const float*)d_in[0];
    const float* Wk = (const float*)d_in[1];
    const float* Wq = (const float*)d_in[2];
    const float* Wv = (const float*)d_in[3];
    float* out = (float*)d_out;

    __half *Qh, *Kh, *Vth, *P, *xh, *Wh;
    float *S;
    cudaGetSymbolAddress((void**)&Qh,  g_Qh);
    cudaGetSymbolAddress((void**)&Kh,  g_Kh);
    cudaGetSymbolAddress((void**)&Vth, g_Vth);
    cudaGetSymbolAddress((void**)&S,   g_S);
    cudaGetSymbolAddress((void**)&P,   g_P);
    cudaGetSymbolAddress((void**)&xh,  g_xh);
    cudaGetSymbolAddress((void**)&Wh,  g_Wh);

    cudaFuncSetAttribute(gemm_hf, cudaFuncAttributeMaxDynamicSharedMemorySize, SMEM_TOTAL);

    const long nX = (long)BATCH * SEQ * DIM;
    const long nW = (long)DIM * DIM;
    __half* Wq_h = Wh + 0 * nW;
    __half* Wk_h = Wh + 1 * nW;
    __half* Wv_h = Wh + 2 * nW;

    // 0) convert inputs to fp16
    convert_f16<<<(int)(nX / 1024), 256>>>(x,  xh);
    convert_f16<<<(int)(nW / 1024), 256>>>(Wq, Wq_h);
    convert_f16<<<(int)(nW / 1024), 256>>>(Wk, Wk_h);
    convert_f16<<<(int)(nW / 1024), 256>>>(Wv, Wv_h);

    const long sX = (long)SEQ * DIM;
    const long sS = (long)SEQ * SEQ;
    const long sV = (long)DIM * SEQ;

    // 1) Q = x @ Wq^T, K = x @ Wk^T   (M=8192, N=1024, K=1024) -> fp16
    {
        dim3 g(DIM / BN, (BATCH * SEQ) / BM, 1);
        gemm_hf<<<g, 256, SMEM_TOTAL>>>(xh, Wq_h, Qh, DIM, DIM, 0, 0, 0, 1.0f, 1);
        gemm_hf<<<g, 256, SMEM_TOTAL>>>(xh, Wk_h, Kh, DIM, DIM, 0, 0, 0, 1.0f, 1);
    }
    // 2) Vt[b] = Wv @ x[b]^T          (M=1024, N=2048, K=1024) -> fp16
    {
        dim3 g(SEQ / BN, DIM / BM, BATCH);
        gemm_hf<<<g, 256, SMEM_TOTAL>>>(Wv_h, xh, Vth, DIM, SEQ, 0, sX, sV, 1.0f, 1);
    }
    // 3) S[b] = (Q[b] @ K[b]^T) / 32  (M=2048, N=2048, K=1024) -> fp32
    {
        dim3 g(SEQ / BN, SEQ / BM, BATCH);
        gemm_hf<<<g, 256, SMEM_TOTAL>>>(Qh, Kh, S, DIM, SEQ, sX, sX, sS, 1.0f / 32.0f, 0);
    }
    // 4) row softmax -> fp16 probs
    softmax_rows<<<BATCH * SEQ, 256>>>(S, P, SEQ);

    // 5) out[b] = P[b] @ Vt[b]^T      (M=2048, N=1024, K=2048) -> fp32 d_out
    {
        dim3 g(DIM / BN, SEQ / BM, BATCH);
        gemm_hf<<<g, 256, SMEM_TOTAL>>>(P, Vth, out, SEQ, DIM, sS, sV, sX, 1.0f, 0);
    }
}